// round 8
// baseline (speedup 1.0000x reference)
#include <cuda_runtime.h>
#include <cstdint>

// Problem constants: B=1024, V=100000, C=1024
#define C_CLUSTERS 1024
#define MAX_B      1024
#define MAX_V      100352
#define NCHUNK     2
#define CH         50000            // elements per chunk (half row)
#define CHP        50048            // padded to multiple of 64
#define SENT_PACK  ((1024u << 16) | (CHP - 1))   // sentinel: c=1024, lpos->zeroed slot

// Scratch (__device__ globals per allocation-free rule)
__device__ float    g_sums[(size_t)MAX_B * C_CLUSTERS];     // per-(b,c) sums
__device__ unsigned g_counts[NCHUNK * C_CLUSTERS];          // hist -> cursor
__device__ unsigned g_sorted[NCHUNK * CHP];                 // packed (c<<16)|lpos
__device__ __align__(16) unsigned short g_idx16[MAX_V];     // compact index

// ---------------------------------------------------------------------------
// Prep kernels (run every launch; ~10us total)
// ---------------------------------------------------------------------------
__global__ void init_kernel(int nsums, int nsorted, int ncounts) {
    int i0 = blockIdx.x * blockDim.x + threadIdx.x;
    int st = gridDim.x * blockDim.x;
    for (int i = i0; i < nsums;   i += st) g_sums[i]   = 0.0f;
    for (int i = i0; i < nsorted; i += st) g_sorted[i] = SENT_PACK;
    for (int i = i0; i < ncounts; i += st) g_counts[i] = 0u;
}

__global__ void idx_hist_kernel(const int* __restrict__ cidx, int V) {
    int i = blockIdx.x * blockDim.x + threadIdx.x;
    if (i < V) {
        int c = cidx[i];
        g_idx16[i] = (unsigned short)c;
        atomicAdd(&g_counts[(i / CH) * C_CLUSTERS + c], 1u);
    }
}

__global__ void scan_kernel() {   // exclusive scan per chunk -> cursor in place
    __shared__ unsigned s[C_CLUSTERS];
    int t = threadIdx.x;
    for (int ch = 0; ch < NCHUNK; ch++) {
        unsigned x = g_counts[ch * C_CLUSTERS + t];
        s[t] = x; __syncthreads();
        for (int d = 1; d < C_CLUSTERS; d <<= 1) {
            unsigned v = (t >= d) ? s[t - d] : 0u;
            __syncthreads();
            s[t] += v;
            __syncthreads();
        }
        g_counts[ch * C_CLUSTERS + t] = s[t] - x;   // exclusive
        __syncthreads();
    }
}

__global__ void scatter_kernel(const int* __restrict__ cidx, int V) {
    int i = blockIdx.x * blockDim.x + threadIdx.x;
    if (i < V) {
        int ch = i / CH, lpos = i - ch * CH;
        int c = cidx[i];
        unsigned p = atomicAdd(&g_counts[ch * C_CLUSTERS + c], 1u);
        g_sorted[ch * CHP + p] = ((unsigned)c << 16) | (unsigned)lpos;
    }
}

// ---------------------------------------------------------------------------
// Fused kernel: cluster of 2 CTAs = one row b. CTA = half row (50K elems).
//  Phase A: coalesced load -> exp -> smem; sorted sweep + segmented warp scan
//           -> sparse global atomics into g_sums[b].
//  cluster.sync; then s_d = log(sums) into smem.
//  Phase B: out = __logf(s_exp[i]) - s_d[c]  (cluster 0 -> log-sigmoid),
//           streaming coalesced writes. Logits read exactly ONCE from DRAM.
// ---------------------------------------------------------------------------
__global__ void __launch_bounds__(512, 1) __cluster_dims__(2, 1, 1)
fused_ab_kernel(const float* __restrict__ logits, float* __restrict__ out, int V) {
    extern __shared__ float smem[];
    float* s_exp = smem;              // CHP floats
    float* s_d   = smem + CHP;        // C_CLUSTERS floats

    const int ch  = blockIdx.x;       // 0/1 within cluster
    const int b   = blockIdx.y;
    const int tid = threadIdx.x;
    const int base = ch * CH;
    const int n    = min(CH, V - base);

    const float* src = logits + (size_t)b * V + base;

    // ---- Phase A load: coalesced read + exp -> smem ----
    const int n4 = n >> 2;
    const float4* src4 = (const float4*)src;
    #pragma unroll 4
    for (int i = tid; i < n4; i += 512) {
        float4 x = src4[i];
        float4 e;
        e.x = __expf(x.x); e.y = __expf(x.y);
        e.z = __expf(x.z); e.w = __expf(x.w);
        *(float4*)&s_exp[i * 4] = e;
    }
    for (int i = (n4 << 2) + tid; i < n; i += 512) s_exp[i] = __expf(src[i]);
    for (int i = n + tid; i < CHP; i += 512) s_exp[i] = 0.0f;   // pad (sentinel slot)
    __syncthreads();

    // ---- Phase A sweep: sorted order, segmented warp reduction ----
    const int lane = tid & 31, warp = tid >> 5;
    const unsigned FULL = 0xffffffffu;
    float* srow = g_sums + (size_t)b * C_CLUSTERS;
    const unsigned* sbase = g_sorted + ch * CHP;

    for (int w = warp; w < CHP / 64; w += 16) {
        uint2 e = *(const uint2*)(sbase + w * 64 + lane * 2);
        unsigned c0 = e.x >> 16, c1 = e.y >> 16;
        float v0 = s_exp[e.x & 0xffffu], v1 = s_exp[e.y & 0xffffu];
        unsigned c = c1; float s;
        if (c0 == c1) s = v0 + v1;
        else { s = v1; if (c0 < C_CLUSTERS) atomicAdd(&srow[c0], v0); } // split pair: direct add
        // segmented inclusive scan over ascending cluster ids
        unsigned pc = __shfl_up_sync(FULL, c, 1);
        bool head = (lane == 0) || (c != pc);
        unsigned hmask = __ballot_sync(FULL, head);
        int hd = 31 - __clz(hmask & ((1u << lane) | ((1u << lane) - 1u)));
        #pragma unroll
        for (int d = 1; d < 32; d <<= 1) {
            float t = __shfl_up_sync(FULL, s, d);
            if (lane - d >= hd) s += t;
        }
        bool tail = (lane == 31) || ((((hmask >> lane) >> 1) & 1u) != 0u);
        if (tail && c < C_CLUSTERS) atomicAdd(&srow[c], s);
    }

    // ---- row-wide sums complete across both CTAs ----
    __threadfence();
    asm volatile("barrier.cluster.arrive.aligned;" ::: "memory");
    asm volatile("barrier.cluster.wait.aligned;"   ::: "memory");

    // ---- log-denominator table into smem ----
    for (int i = tid; i < C_CLUSTERS; i += 512)
        s_d[i] = logf(fmaxf(srow[i], 1e-20f));          // SAFE_LOG_MIN clamp
    __syncthreads();

    // ---- Phase B: streaming output from smem-resident exp ----
    float4* out4 = (float4*)(out + (size_t)b * V + base);
    const ushort4* idx4 = (const ushort4*)(g_idx16 + base);
    #pragma unroll 2
    for (int i = tid; i < n4; i += 512) {
        float4 e = *(const float4*)&s_exp[i * 4];
        ushort4 c = idx4[i];
        float4 x, r;
        x.x = __logf(e.x); x.y = __logf(e.y);
        x.z = __logf(e.z); x.w = __logf(e.w);
        r.x = x.x - s_d[c.x];
        r.y = x.y - s_d[c.y];
        r.z = x.z - s_d[c.z];
        r.w = x.w - s_d[c.w];
        bool need = (c.x == 0) | (c.y == 0) | (c.z == 0) | (c.w == 0);
        if (__any_sync(FULL, need)) {        // rare log-sigmoid path, warp-branched
            if (c.x == 0) r.x = x.x - log1pf(e.x);
            if (c.y == 0) r.y = x.y - log1pf(e.y);
            if (c.z == 0) r.z = x.z - log1pf(e.z);
            if (c.w == 0) r.w = x.w - log1pf(e.w);
        }
        out4[i] = r;
    }
    {   // tail
        float* orow = out + (size_t)b * V + base;
        for (int i = (n4 << 2) + tid; i < n; i += 512) {
            float e = s_exp[i];
            float x = __logf(e);
            unsigned short c = g_idx16[base + i];
            orow[i] = (c == 0) ? (x - log1pf(e)) : (x - s_d[c]);
        }
    }
}

// ---------------------------------------------------------------------------
extern "C" void kernel_launch(void* const* d_in, const int* in_sizes, int n_in,
                              void* d_out, int out_size) {
    const float* logits = (const float*)d_in[0];
    const int*   cidx   = (const int*)d_in[1];
    const int V = in_sizes[1];
    const int B = in_sizes[0] / V;

    static bool attr_set = false;
    const int SMEM_BYTES = (CHP + C_CLUSTERS) * 4;   // 204,288 B
    if (!attr_set) {
        cudaFuncSetAttribute(fused_ab_kernel,
                             cudaFuncAttributeMaxDynamicSharedMemorySize, SMEM_BYTES);
        attr_set = true;
    }

    // prep
    init_kernel<<<512, 256>>>(MAX_B * C_CLUSTERS, NCHUNK * CHP, NCHUNK * C_CLUSTERS);
    {
        int th = 256, bl = (V + th - 1) / th;
        idx_hist_kernel<<<bl, th>>>(cidx, V);
        scan_kernel<<<1, C_CLUSTERS>>>();
        scatter_kernel<<<bl, th>>>(cidx, V);
    }

    // fused segment-sum + output (2-CTA cluster per row)
    dim3 grid(NCHUNK, B, 1);
    fused_ab_kernel<<<grid, 512, SMEM_BYTES>>>(logits, (float*)d_out, V);
}

// round 9
// speedup vs baseline: 2.1828x; 2.1828x over previous
#include <cuda_runtime.h>
#include <cstdint>

// Problem constants: B=1024, V=100000, C=1024
#define C_CLUSTERS 1024
#define MAX_B      1024
#define MAX_V      100352
#define NCHUNK     8
#define CH         12500                       // elements per chunk
#define CHP        12800                       // padded: multiple of 512
#define T_PER_THR  (CHP / 512)                 // 25 sorted entries per thread
#define SENT_PACK  ((1024u << 16) | (CHP - 1)) // sentinel: c=1024 -> guarded, slot zeroed

// Scratch (__device__ globals per allocation-free rule)
__device__ float    g_sums[(size_t)MAX_B * C_CLUSTERS];   // per-(b,c) exp-sums
__device__ unsigned g_counts[NCHUNK * C_CLUSTERS];        // hist -> cursors
__device__ unsigned g_sorted[NCHUNK * CHP];               // packed (c<<16)|lpos, sorted by c
__device__ __align__(16) unsigned short g_idx16[MAX_V];   // compact index for pass2

// ---------------------------------------------------------------------------
// Prep kernels (~20us total, index is row-invariant but recomputed each launch)
// ---------------------------------------------------------------------------
__global__ void init_kernel(int nsums, int nsorted, int ncounts) {
    int i0 = blockIdx.x * blockDim.x + threadIdx.x;
    int st = gridDim.x * blockDim.x;
    for (int i = i0; i < nsums;   i += st) g_sums[i]   = 0.0f;
    for (int i = i0; i < nsorted; i += st) g_sorted[i] = SENT_PACK;
    for (int i = i0; i < ncounts; i += st) g_counts[i] = 0u;
}

__global__ void idx_hist_kernel(const int* __restrict__ cidx, int V) {
    int i = blockIdx.x * blockDim.x + threadIdx.x;
    if (i < V) {
        int c = cidx[i];
        g_idx16[i] = (unsigned short)c;
        atomicAdd(&g_counts[(i / CH) * C_CLUSTERS + c], 1u);
    }
}

__global__ void scan_kernel() {   // per-chunk exclusive scan -> scatter cursors
    __shared__ unsigned s[C_CLUSTERS];
    int t = threadIdx.x;
    for (int ch = 0; ch < NCHUNK; ch++) {
        unsigned x = g_counts[ch * C_CLUSTERS + t];
        s[t] = x; __syncthreads();
        for (int d = 1; d < C_CLUSTERS; d <<= 1) {
            unsigned v = (t >= d) ? s[t - d] : 0u;
            __syncthreads();
            s[t] += v;
            __syncthreads();
        }
        g_counts[ch * C_CLUSTERS + t] = s[t] - x;   // exclusive
        __syncthreads();
    }
}

__global__ void scatter_kernel(const int* __restrict__ cidx, int V) {
    int i = blockIdx.x * blockDim.x + threadIdx.x;
    if (i < V) {
        int ch = i / CH, lpos = i - ch * CH;
        int c = cidx[i];
        unsigned p = atomicAdd(&g_counts[ch * C_CLUSTERS + c], 1u);
        g_sorted[ch * CHP + p] = ((unsigned)c << 16) | (unsigned)lpos;
    }
}

// ---------------------------------------------------------------------------
// Pass 1: segment-sum of exp via sorted sweep. Block = (chunk, row).
//   - coalesced load + exp -> smem
//   - coalesced copy of sorted perm (L2-hot) -> smem
//   - each thread merges 25 consecutive sorted entries by run,
//     one global atomicAdd (no return -> REDG) per run boundary.
// 100KB smem -> 2 CTAs/SM, 32 warps/SM.
// ---------------------------------------------------------------------------
__global__ void __launch_bounds__(512, 2)
pass1_sweep_kernel(const float* __restrict__ logits, int V) {
    extern __shared__ float smem[];
    float*    s_exp  = smem;                          // CHP floats
    unsigned* s_perm = (unsigned*)(smem + CHP);       // CHP words

    const int ch  = blockIdx.x;
    const int b   = blockIdx.y;
    const int tid = threadIdx.x;
    const int base = ch * CH;
    const int n    = min(CH, V - base);
    const float* src = logits + (size_t)b * V + base;

    // load + exp (coalesced, vectorized)
    const int n4 = n >> 2;
    const float4* src4 = (const float4*)src;
    #pragma unroll 4
    for (int i = tid; i < n4; i += 512) {
        float4 x = src4[i];
        float4 e;
        e.x = __expf(x.x); e.y = __expf(x.y);
        e.z = __expf(x.z); e.w = __expf(x.w);
        *(float4*)&s_exp[i * 4] = e;
    }
    for (int i = (n4 << 2) + tid; i < n; i += 512) s_exp[i] = __expf(src[i]);
    for (int i = n + tid; i < CHP; i += 512) s_exp[i] = 0.0f;   // sentinel slots

    // perm -> smem (coalesced uint4)
    const uint4* p4 = (const uint4*)(g_sorted + ch * CHP);
    #pragma unroll 2
    for (int i = tid; i < CHP / 4; i += 512) ((uint4*)s_perm)[i] = p4[i];
    __syncthreads();

    // per-thread run-merge over sorted entries
    float* srow = g_sums + (size_t)b * C_CLUSTERS;
    const int o = tid * T_PER_THR;
    unsigned e0   = s_perm[o];
    unsigned prev = e0 >> 16;
    float    acc  = s_exp[e0 & 0xffffu];
    #pragma unroll
    for (int j = 1; j < T_PER_THR; j++) {
        unsigned e = s_perm[o + j];
        unsigned c = e >> 16;
        float    v = s_exp[e & 0xffffu];
        if (c != prev) {
            if (prev < C_CLUSTERS) atomicAdd(&srow[prev], acc);
            prev = c; acc = v;
        } else {
            acc += v;
        }
    }
    if (prev < C_CLUSTERS) atomicAdd(&srow[prev], acc);
}

// ---------------------------------------------------------------------------
// Pass 2: out[b][v] = x - log(sums[b][c])  (cluster 0 -> log-sigmoid)
// Table log-ed while loading into smem; streaming float4 read/write.
// ---------------------------------------------------------------------------
#define P2_SPLITS 4
__global__ __launch_bounds__(512)
void pass2_kernel(const float* __restrict__ logits, float* __restrict__ out,
                  int B, int V) {
    __shared__ float s_d[C_CLUSTERS];
    const int b = blockIdx.y;
    const float* srow = g_sums + (size_t)b * C_CLUSTERS;
    for (int i = threadIdx.x; i < C_CLUSTERS; i += blockDim.x)
        s_d[i] = logf(fmaxf(srow[i], 1e-20f));          // SAFE_LOG_MIN clamp
    __syncthreads();

    const float* row  = logits + (size_t)b * V;
    float*       orow = out    + (size_t)b * V;

    const int V4 = V >> 2;
    const float4*  row4  = (const float4*)row;
    float4*        orow4 = (float4*)orow;
    const ushort4* idx4  = (const ushort4*)g_idx16;

    const int chunk = (V4 + P2_SPLITS - 1) / P2_SPLITS;
    const int start = blockIdx.x * chunk;
    const int end   = min(start + chunk, V4);

    for (int i = start + (int)threadIdx.x; i < end; i += (int)blockDim.x) {
        float4  x = row4[i];
        ushort4 c = idx4[i];
        float4 r;
        r.x = x.x - s_d[c.x];
        r.y = x.y - s_d[c.y];
        r.z = x.z - s_d[c.z];
        r.w = x.w - s_d[c.w];
        bool need = (c.x == 0) | (c.y == 0) | (c.z == 0) | (c.w == 0);
        if (__any_sync(0xffffffffu, need)) {  // rare log-sigmoid path, warp-branched
            if (c.x == 0) r.x = x.x - log1pf(__expf(x.x));
            if (c.y == 0) r.y = x.y - log1pf(__expf(x.y));
            if (c.z == 0) r.z = x.z - log1pf(__expf(x.z));
            if (c.w == 0) r.w = x.w - log1pf(__expf(x.w));
        }
        orow4[i] = r;
    }
    if (blockIdx.x == P2_SPLITS - 1) {   // tail (V % 4)
        for (int i = (V4 << 2) + (int)threadIdx.x; i < V; i += (int)blockDim.x) {
            float x = row[i];
            unsigned short c = g_idx16[i];
            orow[i] = (c == 0) ? (x - log1pf(__expf(x))) : (x - s_d[c]);
        }
    }
}

// ---------------------------------------------------------------------------
extern "C" void kernel_launch(void* const* d_in, const int* in_sizes, int n_in,
                              void* d_out, int out_size) {
    const float* logits = (const float*)d_in[0];
    const int*   cidx   = (const int*)d_in[1];
    const int V = in_sizes[1];
    const int B = in_sizes[0] / V;

    static bool attr_set = false;
    const int SMEM_BYTES = 2 * CHP * 4;   // 102,400 B
    if (!attr_set) {
        cudaFuncSetAttribute(pass1_sweep_kernel,
                             cudaFuncAttributeMaxDynamicSharedMemorySize, SMEM_BYTES);
        attr_set = true;
    }

    // prep
    init_kernel<<<512, 256>>>(MAX_B * C_CLUSTERS, NCHUNK * CHP, NCHUNK * C_CLUSTERS);
    {
        int th = 256, bl = (V + th - 1) / th;
        idx_hist_kernel<<<bl, th>>>(cidx, V);
        scan_kernel<<<1, C_CLUSTERS>>>();
        scatter_kernel<<<bl, th>>>(cidx, V);
    }

    // pass 1: sorted-sweep segment sums
    {
        dim3 grid(NCHUNK, B, 1);
        pass1_sweep_kernel<<<grid, 512, SMEM_BYTES>>>(logits, V);
    }

    // pass 2: streaming output
    {
        dim3 grid(P2_SPLITS, B, 1);
        pass2_kernel<<<grid, 512>>>(logits, (float*)d_out, B, V);
    }
}